// round 1
// baseline (speedup 1.0000x reference)
#include <cuda_runtime.h>
#include <math.h>
#include <float.h>

#define NBATCH 16
#define NANCH  5
#define NHH    96
#define NWW    96
#define MAXT   50
#define NCLS   40
#define CH     45
#define TSTR   53
#define NCELL  (NHH*NWW)                 // 9216
#define NALL   (NBATCH*NANCH*NCELL)      // 737280
#define NSLOT  (MAXT*NANCH)              // 250 per batch

struct TRec { int cell; int best; int ign; float tx, ty, tw, th; int label; };

__device__ TRec  g_trec[NBATCH*MAXT];
__device__ int   g_slot[NBATCH*NSLOT];   // packed: cell|a<<14|wt<<17|type<<23 (0 = none)

__device__ float g_bceAll, g_corrBce, g_subPc, g_maskBce;
__device__ float g_Sx, g_Sy, g_Sw, g_Sh, g_Sce;
__device__ int   g_corrCnt, g_nM, g_nCorrect, g_nProp;

__device__ __forceinline__ float softplusf(float x) {
    return fmaxf(x, 0.0f) + log1pf(expf(-fabsf(x)));
}

// ---------------- K0: zero accumulators ----------------
__global__ void k_init() {
    if (threadIdx.x == 0) {
        g_bceAll = 0.f; g_corrBce = 0.f; g_subPc = 0.f; g_maskBce = 0.f;
        g_Sx = 0.f; g_Sy = 0.f; g_Sw = 0.f; g_Sh = 0.f; g_Sce = 0.f;
        g_corrCnt = 0; g_nM = 0; g_nCorrect = 0; g_nProp = 0;
    }
}

// ---------------- K1: per-target parallel records + nCorrect (1 warp / target) ----------------
__global__ void k_targets(const float* __restrict__ pred,
                          const float* __restrict__ tgt,
                          const int*   __restrict__ ts) {
    int warp = (blockIdx.x * blockDim.x + threadIdx.x) >> 5;
    int lane = threadIdx.x & 31;
    if (warp >= NBATCH * MAXT) return;
    int b = warp / MAXT, t = warp % MAXT;
    if (t >= ts[b]) return;                       // uniform across warp

    const float aw[NANCH] = {1.f, 2.f, 4.f, 2.f, 4.f};
    const float ah[NANCH] = {1.f, 2.f, 4.f, 4.f, 2.f};

    const float* row = tgt + (size_t)(b * MAXT + t) * TSTR;

    // label = first-argmax of row[13:53] (warp-parallel)
    float lv = -FLT_MAX; int li = NCLS;
    for (int c = lane; c < NCLS; c += 32) {
        float v = row[13 + c];
        if (v > lv) { lv = v; li = c; }
    }
    for (int off = 16; off; off >>= 1) {
        float ov = __shfl_down_sync(0xffffffffu, lv, off);
        int   oi = __shfl_down_sync(0xffffffffu, li, off);
        if (ov > lv || (ov == lv && oi < li)) { lv = ov; li = oi; }
    }
    int label = __shfl_sync(0xffffffffu, li, 0);

    // scalar target math (all lanes redundantly, deterministic)
    float gx = row[0] * 0.0625f;
    float gy = row[1] * 0.0625f;
    float gh = row[3] * 0.0625f;
    float gw = row[4] * 0.0625f;
    int gi = (int)gx;
    int gj = (int)gy;

    float best_iou = -1.f; int best = 0; int ign = 0;
    #pragma unroll
    for (int a = 0; a < NANCH; a++) {
        float inter = fmaxf(fminf(gw, aw[a]) + 1.f, 0.f) * fmaxf(fminf(gh, ah[a]) + 1.f, 0.f);
        float denom = (gw + 1.f) * (gh + 1.f) + (aw[a] + 1.f) * (ah[a] + 1.f) - inter + 1e-16f;
        float iou = inter / denom;
        if (iou > best_iou) { best_iou = iou; best = a; }
        if (iou > 0.5f) ign |= (1 << a);
    }

    // class argmax at the prediction slot (warp-parallel)
    const float* p = pred + (size_t)(((b * NANCH + best) * NHH + gj) * NWW + gi) * CH;
    float cv = -FLT_MAX; int ci = NCLS;
    for (int c = lane; c < NCLS; c += 32) {
        float v = p[5 + c];
        if (v > cv) { cv = v; ci = c; }
    }
    for (int off = 16; off; off >>= 1) {
        float ov = __shfl_down_sync(0xffffffffu, cv, off);
        int   oi = __shfl_down_sync(0xffffffffu, ci, off);
        if (ov > cv || (ov == cv && oi < ci)) { cv = ov; ci = oi; }
    }

    if (lane == 0) {
        float pc = p[0], px = p[1], py = p[2], ph = p[3], pw = p[4];
        float pbx = px + (float)gi;
        float pby = py + (float)gj;
        float pbw = expf(pw) * aw[best];
        float pbh = expf(ph) * ah[best];

        float gx1 = gx - gw * 0.5f, gx2 = gx + gw * 0.5f;
        float gy1 = gy - gh * 0.5f, gy2 = gy + gh * 0.5f;
        float px1 = pbx - pbw * 0.5f, px2 = pbx + pbw * 0.5f;
        float py1 = pby - pbh * 0.5f, py2 = pby + pbh * 0.5f;
        float iw = fmaxf(fminf(gx2, px2) - fmaxf(gx1, px1) + 1.f, 0.f);
        float ih = fmaxf(fminf(gy2, py2) - fmaxf(gy1, py1) + 1.f, 0.f);
        float inter = iw * ih;
        float ga = (gx2 - gx1 + 1.f) * (gy2 - gy1 + 1.f);
        float pa = (px2 - px1 + 1.f) * (py2 - py1 + 1.f);
        float iou = inter / (ga + pa - inter + 1e-16f);

        if (iou > 0.5f && ci == label && pc > 0.5f) atomicAdd(&g_nCorrect, 1);

        TRec r;
        r.cell = gj * NWW + gi;
        r.best = best;
        r.ign  = ign;
        r.tx = gx - (float)gi;
        r.ty = gy - (float)gj;
        r.tw = logf(gw / aw[best] + 1e-16f);
        r.th = logf(gh / ah[best] + 1e-16f);
        r.label = label;
        g_trec[warp] = r;
    }
}

// ---------------- K2: per-batch sequential last-writer resolve ----------------
__global__ void k_resolve(const int* __restrict__ ts) {
    int b = blockIdx.x;
    __shared__ TRec rec[MAXT];
    __shared__ int  cellKey[MAXT];
    __shared__ short B[MAXT * NANCH];
    __shared__ short I[MAXT * NANCH];
    __shared__ int   nc;

    int n = ts[b];
    for (int t = threadIdx.x; t < n; t += blockDim.x)
        rec[t] = g_trec[b * MAXT + t];
    __syncthreads();

    if (threadIdx.x == 0) {
        int m = 0;
        for (int t = 0; t < n; t++) {
            int cell = rec[t].cell;
            int k = -1;
            for (int j = 0; j < m; j++) if (cellKey[j] == cell) { k = j; break; }
            if (k < 0) {
                k = m++;
                cellKey[k] = cell;
                #pragma unroll
                for (int a = 0; a < NANCH; a++) { B[k*NANCH+a] = -1; I[k*NANCH+a] = -1; }
            }
            int ign = rec[t].ign;
            #pragma unroll
            for (int a = 0; a < NANCH; a++)
                if ((ign >> a) & 1) I[k*NANCH+a] = (short)t;
            B[k*NANCH + rec[t].best] = (short)t;
        }
        nc = m;
    }
    __syncthreads();

    int m = nc;
    for (int s = threadIdx.x; s < NSLOT; s += blockDim.x) {
        int out = 0;
        if (s < m * NANCH) {
            int k = s / NANCH, a = s % NANCH;
            int Bv = B[s], Iv = I[s];
            int type;
            if (Bv < 0) type = (Iv < 0) ? 0 : 1;         // 1: cmf==0 (ignored, not best)
            else        type = (Iv <= Bv) ? 2 : 3;        // 2: winner; 3: mask=1,conf=0
            if (type)
                out = cellKey[k] | (a << 14) | ((type == 2 ? Bv : 0) << 17) | (type << 23);
        }
        g_slot[b * NSLOT + s] = out;
    }
}

// ---------------- K3: full-plane conf reduction ----------------
__global__ void __launch_bounds__(256) k_conf(const float* __restrict__ pred) {
    int tid = blockIdx.x * blockDim.x + threadIdx.x;
    int stride = gridDim.x * blockDim.x;
    float s = 0.f; int c = 0;
    for (int i = tid; i < NALL; i += stride) {
        float pc = __ldg(pred + (size_t)i * CH);
        s += softplusf(pc);
        c += (pc > 0.f);
    }
    // warp reduce
    for (int off = 16; off; off >>= 1) {
        s += __shfl_down_sync(0xffffffffu, s, off);
        c += __shfl_down_sync(0xffffffffu, c, off);
    }
    __shared__ float ws[8]; __shared__ int wc[8];
    int lane = threadIdx.x & 31, wid = threadIdx.x >> 5;
    if (lane == 0) { ws[wid] = s; wc[wid] = c; }
    __syncthreads();
    if (wid == 0) {
        s = (lane < 8) ? ws[lane] : 0.f;
        c = (lane < 8) ? wc[lane] : 0;
        for (int off = 4; off; off >>= 1) {
            s += __shfl_down_sync(0xffffffffu, s, off);
            c += __shfl_down_sync(0xffffffffu, c, off);
        }
        if (lane == 0) { atomicAdd(&g_bceAll, s); atomicAdd(&g_nProp, c); }
    }
}

// ---------------- K4: touched-slot corrections + winner losses ----------------
__global__ void k_slots(const float* __restrict__ pred) {
    int s = blockIdx.x * blockDim.x + threadIdx.x;
    if (s >= NBATCH * NSLOT) return;
    int v = g_slot[s];
    if (!v) return;
    int b    = s / NSLOT;
    int cell = v & 0x3FFF;
    int a    = (v >> 14) & 7;
    int wt   = (v >> 17) & 63;
    int type = (v >> 23) & 3;

    const float* p = pred + (size_t)((b * NANCH + a) * NCELL + cell) * CH;
    float pc = p[0];
    float sp = softplusf(pc);

    if (type == 3) { atomicAdd(&g_subPc, pc); return; }     // cmf=1, tconf=1: bce lost -pc
    atomicAdd(&g_corrBce, sp);                               // cmf==0 slot
    atomicAdd(&g_corrCnt, 1);
    if (type == 1) return;

    // winner (mask=1, tconf=1)
    atomicAdd(&g_maskBce, sp - pc);
    atomicAdd(&g_nM, 1);
    TRec r = g_trec[b * MAXT + wt];
    float dx = p[1] - r.tx, dy = p[2] - r.ty;
    float dh = p[3] - r.th, dw = p[4] - r.tw;
    atomicAdd(&g_Sx, dx * dx);
    atomicAdd(&g_Sy, dy * dy);
    atomicAdd(&g_Sw, dw * dw);
    atomicAdd(&g_Sh, dh * dh);

    float mx = -FLT_MAX;
    #pragma unroll
    for (int c = 0; c < NCLS; c++) mx = fmaxf(mx, p[5 + c]);
    float se = 0.f;
    #pragma unroll
    for (int c = 0; c < NCLS; c++) se += expf(p[5 + c] - mx);
    float lse = mx + logf(se);
    atomicAdd(&g_Sce, lse - p[5 + r.label]);
}

// ---------------- K5: finalize ----------------
__global__ void k_final(const int* __restrict__ ts, float* __restrict__ out, int out_size) {
    if (threadIdx.x != 0) return;
    int nGT = 0;
    for (int b = 0; b < NBATCH; b++) nGT += ts[b];
    float nM = (float)g_nM;
    float lx = g_Sx / nM, ly = g_Sy / nM, lw = g_Sw / nM, lh = g_Sh / nM;
    float cmfB = g_bceAll - g_corrBce - g_subPc;
    float cmfC = (float)(NALL - g_corrCnt);
    float lconf = cmfB / cmfC + g_maskBce / nM;
    float lcls  = (1.0f / NBATCH) * g_Sce / nM;
    float coord = lx + ly + lw + lh;
    float loss  = coord + lconf + lcls;
    float nCor  = (float)g_nCorrect;
    int   gtd   = nGT > 1 ? nGT : 1;
    float recall = nCor / (float)gtd;
    float nProp = (float)g_nProp;
    float prec  = (nProp > 0.f) ? (nCor / fmaxf(nProp, 1.f)) : 1.f;
    if (out_size >= 6) {
        out[0] = loss; out[1] = coord; out[2] = lconf;
        out[3] = lcls; out[4] = recall; out[5] = prec;
    }
}

extern "C" void kernel_launch(void* const* d_in, const int* in_sizes, int n_in,
                              void* d_out, int out_size) {
    const float* pred = (const float*)d_in[0];
    const float* tgt  = (const float*)d_in[1];
    const int*   ts   = (const int*)d_in[2];
    float* out = (float*)d_out;

    k_init<<<1, 32>>>();
    k_targets<<<(NBATCH * MAXT * 32 + 255) / 256, 256>>>(pred, tgt, ts);
    k_resolve<<<NBATCH, 64>>>(ts);
    k_conf<<<512, 256>>>(pred);
    k_slots<<<(NBATCH * NSLOT + 255) / 256, 256>>>(pred);
    k_final<<<1, 32>>>(ts, out, out_size);
}

// round 5
// speedup vs baseline: 2.5324x; 2.5324x over previous
#include <cuda_runtime.h>
#include <math.h>
#include <float.h>

#define NBATCH 16
#define NANCH  5
#define NHH    96
#define NWW    96
#define MAXT   50
#define NCLS   40
#define CH     45
#define TSTR   53
#define NCELL  (NHH*NWW)                 // 9216
#define NALL   (NBATCH*NANCH*NCELL)      // 737280
#define NSLOT  (MAXT*NANCH)              // 250 per batch

struct TRec { int cell; int best; int ign; float tx, ty, tw, th; int label; };

__device__ TRec  g_trec[NBATCH*MAXT];
__device__ int   g_slot[NBATCH*NSLOT];   // packed: cell|a<<14|wt<<17|type<<23 (0 = none)

__device__ float g_bceAll, g_corrBce, g_subPc, g_maskBce;
__device__ float g_Sx, g_Sy, g_Sw, g_Sh, g_Sce;
__device__ int   g_corrCnt, g_nM, g_nCorrect, g_nProp;

__device__ __forceinline__ float softplusf(float x) {
    return fmaxf(x, 0.0f) + log1pf(expf(-fabsf(x)));
}

// ---------------- K0: zero accumulators ----------------
__global__ void k_init() {
    if (threadIdx.x == 0) {
        g_bceAll = 0.f; g_corrBce = 0.f; g_subPc = 0.f; g_maskBce = 0.f;
        g_Sx = 0.f; g_Sy = 0.f; g_Sw = 0.f; g_Sh = 0.f; g_Sce = 0.f;
        g_corrCnt = 0; g_nM = 0; g_nCorrect = 0; g_nProp = 0;
    }
}

// ---------------- K1: per-target parallel records + nCorrect (1 warp / target) ----------------
__global__ void k_targets(const float* __restrict__ pred,
                          const float* __restrict__ tgt,
                          const int*   __restrict__ ts) {
    int warp = (blockIdx.x * blockDim.x + threadIdx.x) >> 5;
    int lane = threadIdx.x & 31;
    if (warp >= NBATCH * MAXT) return;
    int b = warp / MAXT, t = warp % MAXT;
    if (t >= ts[b]) return;                       // uniform across warp

    const float aw[NANCH] = {1.f, 2.f, 4.f, 2.f, 4.f};
    const float ah[NANCH] = {1.f, 2.f, 4.f, 4.f, 2.f};

    const float* row = tgt + (size_t)(b * MAXT + t) * TSTR;

    // label = first-argmax of row[13:53] (warp-parallel)
    float lv = -FLT_MAX; int li = NCLS;
    for (int c = lane; c < NCLS; c += 32) {
        float v = row[13 + c];
        if (v > lv) { lv = v; li = c; }
    }
    for (int off = 16; off; off >>= 1) {
        float ov = __shfl_down_sync(0xffffffffu, lv, off);
        int   oi = __shfl_down_sync(0xffffffffu, li, off);
        if (ov > lv || (ov == lv && oi < li)) { lv = ov; li = oi; }
    }
    int label = __shfl_sync(0xffffffffu, li, 0);

    // scalar target math (all lanes redundantly, deterministic)
    float gx = row[0] * 0.0625f;
    float gy = row[1] * 0.0625f;
    float gh = row[3] * 0.0625f;
    float gw = row[4] * 0.0625f;
    int gi = (int)gx;
    int gj = (int)gy;

    float best_iou = -1.f; int best = 0; int ign = 0;
    #pragma unroll
    for (int a = 0; a < NANCH; a++) {
        float inter = fmaxf(fminf(gw, aw[a]) + 1.f, 0.f) * fmaxf(fminf(gh, ah[a]) + 1.f, 0.f);
        float denom = (gw + 1.f) * (gh + 1.f) + (aw[a] + 1.f) * (ah[a] + 1.f) - inter + 1e-16f;
        float iou = inter / denom;
        if (iou > best_iou) { best_iou = iou; best = a; }
        if (iou > 0.5f) ign |= (1 << a);
    }

    // class argmax at the prediction slot (warp-parallel)
    const float* p = pred + (size_t)(((b * NANCH + best) * NHH + gj) * NWW + gi) * CH;
    float cv = -FLT_MAX; int ci = NCLS;
    for (int c = lane; c < NCLS; c += 32) {
        float v = p[5 + c];
        if (v > cv) { cv = v; ci = c; }
    }
    for (int off = 16; off; off >>= 1) {
        float ov = __shfl_down_sync(0xffffffffu, cv, off);
        int   oi = __shfl_down_sync(0xffffffffu, ci, off);
        if (ov > cv || (ov == cv && oi < ci)) { cv = ov; ci = oi; }
    }

    if (lane == 0) {
        float pc = p[0], px = p[1], py = p[2], ph = p[3], pw = p[4];
        float pbx = px + (float)gi;
        float pby = py + (float)gj;
        float pbw = expf(pw) * aw[best];
        float pbh = expf(ph) * ah[best];

        float gx1 = gx - gw * 0.5f, gx2 = gx + gw * 0.5f;
        float gy1 = gy - gh * 0.5f, gy2 = gy + gh * 0.5f;
        float px1 = pbx - pbw * 0.5f, px2 = pbx + pbw * 0.5f;
        float py1 = pby - pbh * 0.5f, py2 = pby + pbh * 0.5f;
        float iw = fmaxf(fminf(gx2, px2) - fmaxf(gx1, px1) + 1.f, 0.f);
        float ih = fmaxf(fminf(gy2, py2) - fmaxf(gy1, py1) + 1.f, 0.f);
        float inter = iw * ih;
        float ga = (gx2 - gx1 + 1.f) * (gy2 - gy1 + 1.f);
        float pa = (px2 - px1 + 1.f) * (py2 - py1 + 1.f);
        float iou = inter / (ga + pa - inter + 1e-16f);

        if (iou > 0.5f && ci == label && pc > 0.5f) atomicAdd(&g_nCorrect, 1);

        TRec r;
        r.cell = gj * NWW + gi;
        r.best = best;
        r.ign  = ign;
        r.tx = gx - (float)gi;
        r.ty = gy - (float)gj;
        r.tw = logf(gw / aw[best] + 1e-16f);
        r.th = logf(gh / ah[best] + 1e-16f);
        r.label = label;
        g_trec[warp] = r;
    }
}

// ---------------- K2: per-batch resolve (PARALLEL per-(t,a) scan; same g_slot output) ----------------
__global__ void k_resolve(const int* __restrict__ ts) {
    int b = blockIdx.x;
    int n = ts[b];
    __shared__ int sc[MAXT], sb[MAXT], si[MAXT];

    for (int t = threadIdx.x; t < n; t += blockDim.x) {
        TRec r = g_trec[b * MAXT + t];
        sc[t] = r.cell; sb[t] = r.best; si[t] = r.ign;
    }
    __syncthreads();

    int s = threadIdx.x;              // (t, a) pair index
    if (s < NSLOT) {
        int out = 0;
        int t = s / NANCH, a = s % NANCH;
        if (t < n) {
            int mycell = sc[t];
            bool firstOcc = true;
            for (int u = 0; u < t; u++) if (sc[u] == mycell) { firstOcc = false; break; }
            if (firstOcc) {
                int Bv = -1, Iv = -1;
                for (int u = 0; u < n; u++) {
                    if (sc[u] == mycell) {
                        if ((si[u] >> a) & 1) Iv = u;
                        if (sb[u] == a)       Bv = u;
                    }
                }
                int type;
                if (Bv < 0) type = (Iv < 0) ? 0 : 1;      // 1: cmf==0 (ignored, not best)
                else        type = (Iv <= Bv) ? 2 : 3;     // 2: winner; 3: mask=1,conf=0
                if (type)
                    out = mycell | (a << 14) | ((type == 2 ? Bv : 0) << 17) | (type << 23);
            }
        }
        g_slot[b * NSLOT + s] = out;
    }
}

// ---------------- K3: full-plane conf reduction ----------------
__global__ void __launch_bounds__(256) k_conf(const float* __restrict__ pred) {
    int tid = blockIdx.x * blockDim.x + threadIdx.x;
    int stride = gridDim.x * blockDim.x;
    float s = 0.f; int c = 0;
    for (int i = tid; i < NALL; i += stride) {
        float pc = __ldg(pred + (size_t)i * CH);
        s += softplusf(pc);
        c += (pc > 0.f);
    }
    // warp reduce
    for (int off = 16; off; off >>= 1) {
        s += __shfl_down_sync(0xffffffffu, s, off);
        c += __shfl_down_sync(0xffffffffu, c, off);
    }
    __shared__ float ws[8]; __shared__ int wc[8];
    int lane = threadIdx.x & 31, wid = threadIdx.x >> 5;
    if (lane == 0) { ws[wid] = s; wc[wid] = c; }
    __syncthreads();
    if (wid == 0) {
        s = (lane < 8) ? ws[lane] : 0.f;
        c = (lane < 8) ? wc[lane] : 0;
        for (int off = 4; off; off >>= 1) {
            s += __shfl_down_sync(0xffffffffu, s, off);
            c += __shfl_down_sync(0xffffffffu, c, off);
        }
        if (lane == 0) { atomicAdd(&g_bceAll, s); atomicAdd(&g_nProp, c); }
    }
}

// ---------------- K4: touched-slot corrections + winner losses ----------------
__global__ void k_slots(const float* __restrict__ pred) {
    int s = blockIdx.x * blockDim.x + threadIdx.x;
    if (s >= NBATCH * NSLOT) return;
    int v = g_slot[s];
    if (!v) return;
    int b    = s / NSLOT;
    int cell = v & 0x3FFF;
    int a    = (v >> 14) & 7;
    int wt   = (v >> 17) & 63;
    int type = (v >> 23) & 3;

    const float* p = pred + (size_t)((b * NANCH + a) * NCELL + cell) * CH;
    float pc = p[0];
    float sp = softplusf(pc);

    if (type == 3) { atomicAdd(&g_subPc, pc); return; }     // cmf=1, tconf=1: bce lost -pc
    atomicAdd(&g_corrBce, sp);                               // cmf==0 slot
    atomicAdd(&g_corrCnt, 1);
    if (type == 1) return;

    // winner (mask=1, tconf=1)
    atomicAdd(&g_maskBce, sp - pc);
    atomicAdd(&g_nM, 1);
    TRec r = g_trec[b * MAXT + wt];
    float dx = p[1] - r.tx, dy = p[2] - r.ty;
    float dh = p[3] - r.th, dw = p[4] - r.tw;
    atomicAdd(&g_Sx, dx * dx);
    atomicAdd(&g_Sy, dy * dy);
    atomicAdd(&g_Sw, dw * dw);
    atomicAdd(&g_Sh, dh * dh);

    float mx = -FLT_MAX;
    #pragma unroll
    for (int c = 0; c < NCLS; c++) mx = fmaxf(mx, p[5 + c]);
    float se = 0.f;
    #pragma unroll
    for (int c = 0; c < NCLS; c++) se += expf(p[5 + c] - mx);
    float lse = mx + logf(se);
    atomicAdd(&g_Sce, lse - p[5 + r.label]);
}

// ---------------- K5: finalize ----------------
__global__ void k_final(const int* __restrict__ ts, float* __restrict__ out, int out_size) {
    if (threadIdx.x != 0) return;
    int nGT = 0;
    for (int b = 0; b < NBATCH; b++) nGT += ts[b];
    float nM = (float)g_nM;
    float lx = g_Sx / nM, ly = g_Sy / nM, lw = g_Sw / nM, lh = g_Sh / nM;
    float cmfB = g_bceAll - g_corrBce - g_subPc;
    float cmfC = (float)(NALL - g_corrCnt);
    float lconf = cmfB / cmfC + g_maskBce / nM;
    float lcls  = (1.0f / NBATCH) * g_Sce / nM;
    float coord = lx + ly + lw + lh;
    float loss  = coord + lconf + lcls;
    float nCor  = (float)g_nCorrect;
    int   gtd   = nGT > 1 ? nGT : 1;
    float recall = nCor / (float)gtd;
    float nProp = (float)g_nProp;
    float prec  = (nProp > 0.f) ? (nCor / fmaxf(nProp, 1.f)) : 1.f;
    if (out_size >= 6) {
        out[0] = loss; out[1] = coord; out[2] = lconf;
        out[3] = lcls; out[4] = recall; out[5] = prec;
    }
}

extern "C" void kernel_launch(void* const* d_in, const int* in_sizes, int n_in,
                              void* d_out, int out_size) {
    const float* pred = (const float*)d_in[0];
    const float* tgt  = (const float*)d_in[1];
    const int*   ts   = (const int*)d_in[2];
    float* out = (float*)d_out;

    k_init<<<1, 32>>>();
    k_targets<<<(NBATCH * MAXT * 32 + 255) / 256, 256>>>(pred, tgt, ts);
    k_resolve<<<NBATCH, 256>>>(ts);
    k_conf<<<1184, 256>>>(pred);
    k_slots<<<(NBATCH * NSLOT + 255) / 256, 256>>>(pred);
    k_final<<<1, 32>>>(ts, out, out_size);
}

// round 6
// speedup vs baseline: 2.7237x; 1.0756x over previous
#include <cuda_runtime.h>
#include <math.h>
#include <float.h>

#define NBATCH 16
#define NANCH  5
#define NHH    96
#define NWW    96
#define MAXT   50
#define NCLS   40
#define CH     45
#define TSTR   53
#define NCELL  (NHH*NWW)                 // 9216
#define NALL   (NBATCH*NANCH*NCELL)      // 737280
#define NSLOT  (MAXT*NANCH)              // 250 per batch
#define CONF_GRID   720
#define CONF_BLOCK  256
#define CONF_THREADS (CONF_GRID*CONF_BLOCK)   // 184320; NALL/CONF_THREADS == 4 exactly

struct TRec { int cell; int best; int ign; int label; int correct; float tx, ty, tw, th; };

__device__ TRec  g_trec[NBATCH*MAXT];
__device__ int   g_slot[NBATCH*NSLOT];   // packed: cell|a<<14|wt<<17|type<<23 (0 = none)

__device__ float g_bceAll, g_corrBce, g_subPc, g_maskBce;
__device__ float g_Sx, g_Sy, g_Sw, g_Sh, g_Sce;
__device__ int   g_corrCnt, g_nM, g_nCorrect, g_nProp;

__device__ __forceinline__ float softplusf(float x) {
    return fmaxf(x, 0.0f) + log1pf(expf(-fabsf(x)));
}

// ================= K1: init (block0/thread0; no concurrent writers) + per-target records =========
__global__ void k_targets(const float* __restrict__ pred,
                          const float* __restrict__ tgt,
                          const int*   __restrict__ ts) {
    if (blockIdx.x == 0 && threadIdx.x == 0) {
        g_bceAll = 0.f; g_corrBce = 0.f; g_subPc = 0.f; g_maskBce = 0.f;
        g_Sx = 0.f; g_Sy = 0.f; g_Sw = 0.f; g_Sh = 0.f; g_Sce = 0.f;
        g_corrCnt = 0; g_nM = 0; g_nCorrect = 0; g_nProp = 0;
    }

    int warp = (blockIdx.x * blockDim.x + threadIdx.x) >> 5;
    int lane = threadIdx.x & 31;
    if (warp >= NBATCH * MAXT) return;
    int b = warp / MAXT, t = warp % MAXT;
    if (t >= ts[b]) return;                       // uniform across warp

    const float aw[NANCH] = {1.f, 2.f, 4.f, 2.f, 4.f};
    const float ah[NANCH] = {1.f, 2.f, 4.f, 4.f, 2.f};

    const float* row = tgt + (size_t)(b * MAXT + t) * TSTR;

    // label = first-argmax of row[13:53] (warp-parallel)
    float lv = -FLT_MAX; int li = NCLS;
    for (int c = lane; c < NCLS; c += 32) {
        float v = row[13 + c];
        if (v > lv) { lv = v; li = c; }
    }
    for (int off = 16; off; off >>= 1) {
        float ov = __shfl_down_sync(0xffffffffu, lv, off);
        int   oi = __shfl_down_sync(0xffffffffu, li, off);
        if (ov > lv || (ov == lv && oi < li)) { lv = ov; li = oi; }
    }
    int label = __shfl_sync(0xffffffffu, li, 0);

    float gx = row[0] * 0.0625f;
    float gy = row[1] * 0.0625f;
    float gh = row[3] * 0.0625f;
    float gw = row[4] * 0.0625f;
    int gi = (int)gx;
    int gj = (int)gy;

    float best_iou = -1.f; int best = 0; int ign = 0;
    #pragma unroll
    for (int a = 0; a < NANCH; a++) {
        float inter = fmaxf(fminf(gw, aw[a]) + 1.f, 0.f) * fmaxf(fminf(gh, ah[a]) + 1.f, 0.f);
        float denom = (gw + 1.f) * (gh + 1.f) + (aw[a] + 1.f) * (ah[a] + 1.f) - inter + 1e-16f;
        float iou = inter / denom;
        if (iou > best_iou) { best_iou = iou; best = a; }
        if (iou > 0.5f) ign |= (1 << a);
    }

    const float* p = pred + (size_t)(((b * NANCH + best) * NHH + gj) * NWW + gi) * CH;
    float cv = -FLT_MAX; int ci = NCLS;
    for (int c = lane; c < NCLS; c += 32) {
        float v = p[5 + c];
        if (v > cv) { cv = v; ci = c; }
    }
    for (int off = 16; off; off >>= 1) {
        float ov = __shfl_down_sync(0xffffffffu, cv, off);
        int   oi = __shfl_down_sync(0xffffffffu, ci, off);
        if (ov > cv || (ov == cv && oi < ci)) { cv = ov; ci = oi; }
    }

    if (lane == 0) {
        float pc = p[0], px = p[1], py = p[2], ph = p[3], pw = p[4];
        float pbx = px + (float)gi;
        float pby = py + (float)gj;
        float pbw = expf(pw) * aw[best];
        float pbh = expf(ph) * ah[best];

        float gx1 = gx - gw * 0.5f, gx2 = gx + gw * 0.5f;
        float gy1 = gy - gh * 0.5f, gy2 = gy + gh * 0.5f;
        float px1 = pbx - pbw * 0.5f, px2 = pbx + pbw * 0.5f;
        float py1 = pby - pbh * 0.5f, py2 = pby + pbh * 0.5f;
        float iw = fmaxf(fminf(gx2, px2) - fmaxf(gx1, px1) + 1.f, 0.f);
        float ih = fmaxf(fminf(gy2, py2) - fmaxf(gy1, py1) + 1.f, 0.f);
        float inter = iw * ih;
        float ga = (gx2 - gx1 + 1.f) * (gy2 - gy1 + 1.f);
        float pa = (px2 - px1 + 1.f) * (py2 - py1 + 1.f);
        float iou = inter / (ga + pa - inter + 1e-16f);

        TRec r;
        r.cell = gj * NWW + gi;
        r.best = best;
        r.ign  = ign;
        r.label = label;
        r.correct = (iou > 0.5f && ci == label && pc > 0.5f) ? 1 : 0;
        r.tx = gx - (float)gi;
        r.ty = gy - (float)gj;
        r.tw = logf(gw / aw[best] + 1e-16f);
        r.th = logf(gh / ah[best] + 1e-16f);
        g_trec[warp] = r;
    }
}

// ================= K2: conf reduction (all blocks) + per-batch resolve (blocks < 16) =========
__global__ void __launch_bounds__(CONF_BLOCK) k_resolveconf(const float* __restrict__ pred,
                                                            const int*   __restrict__ ts) {
    // ---- conf plane: exactly 4 elements per thread, independent loads ----
    {
        int tid = blockIdx.x * blockDim.x + threadIdx.x;   // 0 .. 184319
        float s = 0.f; int c = 0;
        #pragma unroll
        for (int k = 0; k < 4; k++) {
            const float* ap = pred + (size_t)(tid + k * CONF_THREADS) * CH;
            float pc;
            asm volatile("ld.global.nc.L2::64B.f32 %0, [%1];" : "=f"(pc) : "l"(ap));
            s += softplusf(pc);
            c += (pc > 0.f);
        }
        for (int off = 16; off; off >>= 1) {
            s += __shfl_down_sync(0xffffffffu, s, off);
            c += __shfl_down_sync(0xffffffffu, c, off);
        }
        __shared__ float ws[8]; __shared__ int wc[8];
        int lane = threadIdx.x & 31, wid = threadIdx.x >> 5;
        if (lane == 0) { ws[wid] = s; wc[wid] = c; }
        __syncthreads();
        if (wid == 0) {
            s = (lane < 8) ? ws[lane] : 0.f;
            c = (lane < 8) ? wc[lane] : 0;
            for (int off = 4; off; off >>= 1) {
                s += __shfl_down_sync(0xffffffffu, s, off);
                c += __shfl_down_sync(0xffffffffu, c, off);
            }
            if (lane == 0) { atomicAdd(&g_bceAll, s); atomicAdd(&g_nProp, c); }
        }
    }

    // ---- resolve: block-uniform branch, verbatim R5 logic + nCorrect from flags ----
    if (blockIdx.x < NBATCH) {
        int b = blockIdx.x;
        int n = ts[b];
        __shared__ int sc[MAXT], sb[MAXT], si[MAXT];

        for (int t = threadIdx.x; t < n; t += blockDim.x) {
            TRec r = g_trec[b * MAXT + t];
            sc[t] = r.cell; sb[t] = r.best; si[t] = r.ign;
            if (r.correct) atomicAdd(&g_nCorrect, 1);
        }
        __syncthreads();

        int s = threadIdx.x;              // (t, a) pair index
        if (s < NSLOT) {
            int out = 0;
            int t = s / NANCH, a = s % NANCH;
            if (t < n) {
                int mycell = sc[t];
                bool firstOcc = true;
                for (int u = 0; u < t; u++) if (sc[u] == mycell) { firstOcc = false; break; }
                if (firstOcc) {
                    int Bv = -1, Iv = -1;
                    for (int u = 0; u < n; u++) {
                        if (sc[u] == mycell) {
                            if ((si[u] >> a) & 1) Iv = u;
                            if (sb[u] == a)       Bv = u;
                        }
                    }
                    int type;
                    if (Bv < 0) type = (Iv < 0) ? 0 : 1;      // 1: cmf==0 (ignored, not best)
                    else        type = (Iv <= Bv) ? 2 : 3;     // 2: winner; 3: mask=1,conf=0
                    if (type)
                        out = mycell | (a << 14) | ((type == 2 ? Bv : 0) << 17) | (type << 23);
                }
            }
            g_slot[b * NSLOT + s] = out;
        }
    }
}

// ================= K3: touched-slot corrections + winner losses =========
__global__ void k_slots(const float* __restrict__ pred) {
    int s = blockIdx.x * blockDim.x + threadIdx.x;
    if (s >= NBATCH * NSLOT) return;
    int v = g_slot[s];
    if (!v) return;
    int b    = s / NSLOT;
    int cell = v & 0x3FFF;
    int a    = (v >> 14) & 7;
    int wt   = (v >> 17) & 63;
    int type = (v >> 23) & 3;

    const float* p = pred + (size_t)((b * NANCH + a) * NCELL + cell) * CH;
    float pc = p[0];
    float sp = softplusf(pc);

    if (type == 3) { atomicAdd(&g_subPc, pc); return; }     // cmf=1, tconf=1: bce lost -pc
    atomicAdd(&g_corrBce, sp);                               // cmf==0 slot
    atomicAdd(&g_corrCnt, 1);
    if (type == 1) return;

    // winner (mask=1, tconf=1)
    atomicAdd(&g_maskBce, sp - pc);
    atomicAdd(&g_nM, 1);
    TRec r = g_trec[b * MAXT + wt];
    float dx = p[1] - r.tx, dy = p[2] - r.ty;
    float dh = p[3] - r.th, dw = p[4] - r.tw;
    atomicAdd(&g_Sx, dx * dx);
    atomicAdd(&g_Sy, dy * dy);
    atomicAdd(&g_Sw, dw * dw);
    atomicAdd(&g_Sh, dh * dh);

    float mx = -FLT_MAX;
    #pragma unroll
    for (int c = 0; c < NCLS; c++) mx = fmaxf(mx, p[5 + c]);
    float se = 0.f;
    #pragma unroll
    for (int c = 0; c < NCLS; c++) se += expf(p[5 + c] - mx);
    float lse = mx + logf(se);
    atomicAdd(&g_Sce, lse - p[5 + r.label]);
}

// ================= K4: finalize =========
__global__ void k_final(const int* __restrict__ ts, float* __restrict__ out, int out_size) {
    if (threadIdx.x != 0) return;
    int nGT = 0;
    for (int b = 0; b < NBATCH; b++) nGT += ts[b];
    float nM = (float)g_nM;
    float lx = g_Sx / nM, ly = g_Sy / nM, lw = g_Sw / nM, lh = g_Sh / nM;
    float cmfB = g_bceAll - g_corrBce - g_subPc;
    float cmfC = (float)(NALL - g_corrCnt);
    float lconf = cmfB / cmfC + g_maskBce / nM;
    float lcls  = (1.0f / NBATCH) * g_Sce / nM;
    float coord = lx + ly + lw + lh;
    float loss  = coord + lconf + lcls;
    float nCor  = (float)g_nCorrect;
    int   gtd   = nGT > 1 ? nGT : 1;
    float recall = nCor / (float)gtd;
    float nProp = (float)g_nProp;
    float prec  = (nProp > 0.f) ? (nCor / fmaxf(nProp, 1.f)) : 1.f;
    if (out_size >= 6) {
        out[0] = loss; out[1] = coord; out[2] = lconf;
        out[3] = lcls; out[4] = recall; out[5] = prec;
    }
}

extern "C" void kernel_launch(void* const* d_in, const int* in_sizes, int n_in,
                              void* d_out, int out_size) {
    const float* pred = (const float*)d_in[0];
    const float* tgt  = (const float*)d_in[1];
    const int*   ts   = (const int*)d_in[2];
    float* out = (float*)d_out;

    k_targets<<<(NBATCH * MAXT * 32 + 255) / 256, 256>>>(pred, tgt, ts);
    k_resolveconf<<<CONF_GRID, CONF_BLOCK>>>(pred, ts);
    k_slots<<<(NBATCH * NSLOT + 255) / 256, 256>>>(pred);
    k_final<<<1, 32>>>(ts, out, out_size);
}